// round 5
// baseline (speedup 1.0000x reference)
#include <cuda_runtime.h>

#define HH 256
#define WW 256
#define D4 64            // 256 channels as float4 (for fixups/gather views)
#define NB 2048
#define KW 8             // channel words (floats) per block
#define RS 264           // smem row stride in words: 8*33, 264 % 32 == 8

// 64 MB tile-partial SAT + cum tables (2MB + 2MB + 64KB).
__device__ float4 g_part[(size_t)HH * WW * D4];
__device__ float4 g_rowcum[8 * 8 * 32 * D4];   // [ti][tj][r][d4]
__device__ float4 g_colcum[8 * 8 * 32 * D4];   // [ti][tj][c][d4]
__device__ float4 g_blockcum[8 * 8 * D4];      // [ti][tj][d4]

__device__ __forceinline__ void acc4(float4& a, const float4 v) {
    a.x += v.x; a.y += v.y; a.z += v.z; a.w += v.w;
}

// ---------------------------------------------------------------------------
// Tile SAT, fully fused: 32x32 pixels x 8 channels per block, 2048 blocks.
// Phase A: row prefix accumulated in a register while streaming feat from
// gmem; only the scanned value touches smem (one STS per element).
// Phase B: col prefix accumulated in a register while streaming smem out to
// g_part (one LDS per element). Both phases bank-conflict-free.
// ---------------------------------------------------------------------------
__global__ void __launch_bounds__(256) sat_tile(const float* __restrict__ feat) {
    __shared__ float sm[32 * RS];                 // 33792 B -> 6 blocks/SM
    int b    = blockIdx.x;
    int dgrp = b & 31;                            // 32 channel groups of 8
    int tj   = (b >> 5) & 7;
    int ti   = b >> 8;
    int t    = threadIdx.x;
    int kw   = t & (KW - 1);
    int u    = t >> 3;                            // 0..31: row (A) / col (B)
    int h0 = ti * 32, w0 = tj * 32, d0 = dgrp * KW;

    // Phase A: row scan. unit (r=u, kw). warp = 4 consecutive r x 8 kw.
    {
        const float* __restrict__ src =
            feat + ((size_t)(h0 + u) * WW + w0) * 256 + d0 + kw;
        float acc = 0.0f;
#pragma unroll
        for (int c = 0; c < 32; ++c) {
            acc += __ldcs(&src[(size_t)c * 256]);  // read-once: evict-first
            sm[u * RS + c * KW + kw] = acc;
        }
    }
    __syncthreads();

    // Phase B: col scan. unit (c=u, kw). Stores final tile-partial SAT.
    {
        float* __restrict__ dst = reinterpret_cast<float*>(g_part) +
            ((size_t)h0 * WW + w0 + u) * 256 + d0 + kw;
        float acc = 0.0f;
#pragma unroll
        for (int r = 0; r < 32; ++r) {
            acc += sm[r * RS + u * KW + kw];
            dst[(size_t)r * WW * 256] = acc;
        }
    }
}

// ---------------------------------------------------------------------------
// Fixups: rowcum / colcum / blockcum from tile edges in g_part.
// Unconditional loads (MLP=7) + predicated adds.
// ---------------------------------------------------------------------------
__global__ void __launch_bounds__(256) fixups() {
    int flat = blockIdx.x * 256 + threadIdx.x;
    if (flat < 131072) {                       // rowcum: left strip sums at row r
        int d4 = flat & 63, r = (flat >> 6) & 31, tj = (flat >> 11) & 7, ti = flat >> 14;
        float4 acc = make_float4(0.f, 0.f, 0.f, 0.f);
#pragma unroll
        for (int s = 0; s < 7; ++s) {
            float4 v = g_part[((size_t)(ti * 32 + r) * WW + s * 32 + 31) * D4 + d4];
            if (s < tj) acc4(acc, v);
        }
        g_rowcum[((ti * 8 + tj) * 32 + r) * 64 + d4] = acc;
    } else if (flat < 262144) {                // colcum: above strip sums at col c
        int f = flat - 131072;
        int d4 = f & 63, c = (f >> 6) & 31, tj = (f >> 11) & 7, ti = f >> 14;
        float4 acc = make_float4(0.f, 0.f, 0.f, 0.f);
#pragma unroll
        for (int s = 0; s < 7; ++s) {
            float4 v = g_part[((size_t)(s * 32 + 31) * WW + tj * 32 + c) * D4 + d4];
            if (s < ti) acc4(acc, v);
        }
        g_colcum[((ti * 8 + tj) * 32 + c) * 64 + d4] = acc;
    } else {                                   // blockcum: 2D prefix of tile totals
        int f = flat - 262144;
        int d4 = f & 63, tj = (f >> 6) & 7, ti = f >> 9;
        float4 acc = make_float4(0.f, 0.f, 0.f, 0.f);
#pragma unroll
        for (int si = 0; si < 7; ++si)
#pragma unroll
            for (int sj = 0; sj < 7; ++sj) {
                float4 v = g_part[((size_t)(si * 32 + 31) * WW + sj * 32 + 31) * D4 + d4];
                if (si < ti && sj < tj) acc4(acc, v);
            }
        g_blockcum[(ti * 8 + tj) * 64 + d4] = acc;
    }
}

// Full SAT(r, c) = tile partial + left strip + above strip + above-left blocks.
__device__ __forceinline__ float4 satval(int r, int c, int d4) {
    int ti = r >> 5, tj = c >> 5;
    float4 v = g_part[((size_t)r * WW + c) * D4 + d4];
    acc4(v, g_rowcum[((ti * 8 + tj) * 32 + (r & 31)) * 64 + d4]);
    acc4(v, g_colcum[((ti * 8 + tj) * 32 + (c & 31)) * 64 + d4]);
    acc4(v, g_blockcum[(ti * 8 + tj) * 64 + d4]);
    return v;
}

// ---------------------------------------------------------------------------
// Gather: 4 boxes per block, 64 float4 lanes per box, <=16 corner loads (L2).
// ---------------------------------------------------------------------------
__global__ void __launch_bounds__(256) roi_gather(const float* __restrict__ boxes,
                                                  float4* __restrict__ out) {
    int n  = blockIdx.x * 4 + (threadIdx.x >> 6);
    int d4 = threadIdx.x & 63;

    float x1 = boxes[n * 4 + 0];
    float y1 = boxes[n * 4 + 1];
    float x2 = boxes[n * 4 + 2];
    float y2 = boxes[n * 4 + 3];

    // _bounds: lo = max(0, floor(lo_f*256)); hi = rint(hi_f*256 + 0.5)
    //          hi = min(256, max(lo+1, hi)). No FMA contraction (match jax).
    int clo = max(0, (int)floorf(__fmul_rn(x1, 256.0f)));
    int chi = (int)rintf(__fadd_rn(__fmul_rn(x2, 256.0f), 0.5f));
    chi = min(WW, max(clo + 1, chi));

    int rlo = max(0, (int)floorf(__fmul_rn(y1, 256.0f)));
    int rhi = (int)rintf(__fadd_rn(__fmul_rn(y2, 256.0f), 0.5f));
    rhi = min(HH, max(rlo + 1, rhi));

    float4 s = satval(rhi - 1, chi - 1, d4);
    if (rlo > 0) {
        float4 a = satval(rlo - 1, chi - 1, d4);
        s.x -= a.x; s.y -= a.y; s.z -= a.z; s.w -= a.w;
    }
    if (clo > 0) {
        float4 bb = satval(rhi - 1, clo - 1, d4);
        s.x -= bb.x; s.y -= bb.y; s.z -= bb.z; s.w -= bb.w;
        if (rlo > 0) acc4(s, satval(rlo - 1, clo - 1, d4));
    }

    float inv = 1.0f / (float)((rhi - rlo) * (chi - clo));
    s.x *= inv; s.y *= inv; s.z *= inv; s.w *= inv;
    out[(size_t)n * D4 + d4] = s;
}

extern "C" void kernel_launch(void* const* d_in, const int* in_sizes, int n_in,
                              void* d_out, int out_size) {
    const float* feat  = (const float*)d_in[0];    // (256,256,256) fp32
    const float* boxes = (const float*)d_in[1];    // (2048,4) fp32
    float4* out = (float4*)d_out;                  // (2048,256) fp32

    sat_tile<<<2048, 256>>>(feat);
    fixups<<<1040, 256>>>();                       // 262144 + 4096 threads
    roi_gather<<<NB / 4, 256>>>(boxes, out);
}

// round 6
// speedup vs baseline: 1.1576x; 1.1576x over previous
#include <cuda_runtime.h>

#define HH 256
#define WW 256
#define D4 64            // 256 channels as float4
#define NB 2048
#define RS 528           // smem row stride in words: 528 % 32 == 16

// 64 MB tile-partial SAT + cum tables (2MB + 2MB + 64KB).
__device__ float4 g_part[(size_t)HH * WW * D4];
__device__ float4 g_rowcum[8 * 8 * 32 * D4];   // [ti][tj][r][d4]
__device__ float4 g_colcum[8 * 8 * 32 * D4];   // [ti][tj][c][d4]
__device__ float4 g_blockcum[8 * 8 * D4];      // [ti][tj][d4]

__device__ __forceinline__ void acc4(float4& a, const float4 v) {
    a.x += v.x; a.y += v.y; a.z += v.z; a.w += v.w;
}

// ---------------------------------------------------------------------------
// Tile SAT, fused + vectorized: 32x32 pixels x 16 channels per block,
// 1024 blocks x 128 threads. Thread = (line u, float4-word kw4).
// Phase A: row prefix in a register while streaming feat (LDG.128, 64B
// contiguity -> 1 wavefront / 64 B); one STS.128 per element (conflict-free).
// Phase B: col prefix in a register while streaming smem out to g_part
// (one LDS.128 per element, conflict-free; STG.128).
// ---------------------------------------------------------------------------
__global__ void __launch_bounds__(128) sat_tile(const float4* __restrict__ feat) {
    extern __shared__ float sm[];                 // 32 * RS words = 67584 B
    int b    = blockIdx.x;
    int dgrp = b & 15;                            // 16 channel groups of 16
    int tj   = (b >> 4) & 7;
    int ti   = b >> 7;
    int t    = threadIdx.x;
    int kw4  = t & 3;                             // float4 word within group
    int u    = t >> 2;                            // 0..31: row (A) / col (B)
    int h0 = ti * 32, w0 = tj * 32;
    int c0 = dgrp * 4;                            // channel offset in float4 units

    // Phase A: row scan. warp = 8 consecutive rows x 4 kw4.
    {
        const float4* __restrict__ src =
            feat + ((size_t)(h0 + u) * WW + w0) * D4 + c0 + kw4;
        float4 acc = make_float4(0.f, 0.f, 0.f, 0.f);
#pragma unroll 8
        for (int c = 0; c < 32; ++c) {
            float4 v = __ldcs(&src[(size_t)c * D4]);
            acc4(acc, v);
            *reinterpret_cast<float4*>(&sm[u * RS + c * 16 + kw4 * 4]) = acc;
        }
    }
    __syncthreads();

    // Phase B: col scan. warp = 8 consecutive cols x 4 kw4.
    {
        float4* __restrict__ dst =
            g_part + ((size_t)h0 * WW + w0 + u) * D4 + c0 + kw4;
        float4 acc = make_float4(0.f, 0.f, 0.f, 0.f);
#pragma unroll 8
        for (int r = 0; r < 32; ++r) {
            acc4(acc, *reinterpret_cast<const float4*>(&sm[r * RS + u * 16 + kw4 * 4]));
            dst[(size_t)r * WW * D4] = acc;
        }
    }
}

// ---------------------------------------------------------------------------
// Fixups: rowcum / colcum / blockcum from tile edges in g_part (L2-resident).
// Unconditional loads (MLP=7) + predicated adds.
// ---------------------------------------------------------------------------
__global__ void __launch_bounds__(256) fixups() {
    int flat = blockIdx.x * 256 + threadIdx.x;
    if (flat < 131072) {                       // rowcum: left strip sums at row r
        int d4 = flat & 63, r = (flat >> 6) & 31, tj = (flat >> 11) & 7, ti = flat >> 14;
        float4 acc = make_float4(0.f, 0.f, 0.f, 0.f);
#pragma unroll
        for (int s = 0; s < 7; ++s) {
            float4 v = g_part[((size_t)(ti * 32 + r) * WW + s * 32 + 31) * D4 + d4];
            if (s < tj) acc4(acc, v);
        }
        g_rowcum[((ti * 8 + tj) * 32 + r) * 64 + d4] = acc;
    } else if (flat < 262144) {                // colcum: above strip sums at col c
        int f = flat - 131072;
        int d4 = f & 63, c = (f >> 6) & 31, tj = (f >> 11) & 7, ti = f >> 14;
        float4 acc = make_float4(0.f, 0.f, 0.f, 0.f);
#pragma unroll
        for (int s = 0; s < 7; ++s) {
            float4 v = g_part[((size_t)(s * 32 + 31) * WW + tj * 32 + c) * D4 + d4];
            if (s < ti) acc4(acc, v);
        }
        g_colcum[((ti * 8 + tj) * 32 + c) * 64 + d4] = acc;
    } else {                                   // blockcum: 2D prefix of tile totals
        int f = flat - 262144;
        int d4 = f & 63, tj = (f >> 6) & 7, ti = f >> 9;
        float4 acc = make_float4(0.f, 0.f, 0.f, 0.f);
#pragma unroll
        for (int si = 0; si < 7; ++si)
#pragma unroll
            for (int sj = 0; sj < 7; ++sj) {
                float4 v = g_part[((size_t)(si * 32 + 31) * WW + sj * 32 + 31) * D4 + d4];
                if (si < ti && sj < tj) acc4(acc, v);
            }
        g_blockcum[(ti * 8 + tj) * 64 + d4] = acc;
    }
}

// Full SAT(r, c) = tile partial + left strip + above strip + above-left blocks.
__device__ __forceinline__ float4 satval(int r, int c, int d4) {
    int ti = r >> 5, tj = c >> 5;
    float4 v = g_part[((size_t)r * WW + c) * D4 + d4];
    acc4(v, g_rowcum[((ti * 8 + tj) * 32 + (r & 31)) * 64 + d4]);
    acc4(v, g_colcum[((ti * 8 + tj) * 32 + (c & 31)) * 64 + d4]);
    acc4(v, g_blockcum[(ti * 8 + tj) * 64 + d4]);
    return v;
}

// ---------------------------------------------------------------------------
// Gather: 4 boxes per block, 64 float4 lanes per box, <=16 corner loads (L2).
// ---------------------------------------------------------------------------
__global__ void __launch_bounds__(256) roi_gather(const float* __restrict__ boxes,
                                                  float4* __restrict__ out) {
    int n  = blockIdx.x * 4 + (threadIdx.x >> 6);
    int d4 = threadIdx.x & 63;

    float x1 = boxes[n * 4 + 0];
    float y1 = boxes[n * 4 + 1];
    float x2 = boxes[n * 4 + 2];
    float y2 = boxes[n * 4 + 3];

    // _bounds: lo = max(0, floor(lo_f*256)); hi = rint(hi_f*256 + 0.5)
    //          hi = min(256, max(lo+1, hi)). No FMA contraction (match jax).
    int clo = max(0, (int)floorf(__fmul_rn(x1, 256.0f)));
    int chi = (int)rintf(__fadd_rn(__fmul_rn(x2, 256.0f), 0.5f));
    chi = min(WW, max(clo + 1, chi));

    int rlo = max(0, (int)floorf(__fmul_rn(y1, 256.0f)));
    int rhi = (int)rintf(__fadd_rn(__fmul_rn(y2, 256.0f), 0.5f));
    rhi = min(HH, max(rlo + 1, rhi));

    float4 s = satval(rhi - 1, chi - 1, d4);
    if (rlo > 0) {
        float4 a = satval(rlo - 1, chi - 1, d4);
        s.x -= a.x; s.y -= a.y; s.z -= a.z; s.w -= a.w;
    }
    if (clo > 0) {
        float4 bb = satval(rhi - 1, clo - 1, d4);
        s.x -= bb.x; s.y -= bb.y; s.z -= bb.z; s.w -= bb.w;
        if (rlo > 0) acc4(s, satval(rlo - 1, clo - 1, d4));
    }

    float inv = 1.0f / (float)((rhi - rlo) * (chi - clo));
    s.x *= inv; s.y *= inv; s.z *= inv; s.w *= inv;
    out[(size_t)n * D4 + d4] = s;
}

extern "C" void kernel_launch(void* const* d_in, const int* in_sizes, int n_in,
                              void* d_out, int out_size) {
    const float4* feat  = (const float4*)d_in[0];   // (256,256,256) fp32
    const float*  boxes = (const float*)d_in[1];    // (2048,4) fp32
    float4* out = (float4*)d_out;                   // (2048,256) fp32

    const int smem = 32 * RS * 4;                   // 67584 B -> 3 blocks/SM
    cudaFuncSetAttribute(sat_tile, cudaFuncAttributeMaxDynamicSharedMemorySize, smem);

    sat_tile<<<1024, 128, smem>>>(feat);
    fixups<<<1040, 256>>>();                        // 262144 + 4096 threads
    roi_gather<<<NB / 4, 256>>>(boxes, out);
}

// round 7
// speedup vs baseline: 1.1641x; 1.0056x over previous
#include <cuda_runtime.h>

#define HH 256
#define WW 256
#define D4 64            // 256 channels as float4
#define NB 2048
#define RS 528           // smem row stride in words: 528 % 32 == 16

// 64 MB tile-partial SAT + cum tables (2MB + 2MB + 64KB).
__device__ float4 g_part[(size_t)HH * WW * D4];
__device__ float4 g_rowcum[8 * 8 * 32 * D4];   // [ti][tj][r][d4]
__device__ float4 g_colcum[8 * 8 * 32 * D4];   // [ti][tj][c][d4]
__device__ float4 g_blockcum[8 * 8 * D4];      // [ti][tj][d4]

__device__ __forceinline__ void acc4(float4& a, const float4 v) {
    a.x += v.x; a.y += v.y; a.z += v.z; a.w += v.w;
}

// ---------------------------------------------------------------------------
// Tile SAT, fused + vectorized + software-pipelined:
// 32x32 pixels x 16 channels per block, 1024 blocks x 128 threads.
// Phase A: batches of 8 independent LDG.128 into a register array (MLP=8,
// 4KB in flight per warp), then row-prefix accumulate + STS.128.
// Phase B: batches of 8 LDS.128, col-prefix accumulate, STG.128 to g_part.
// smem stride 528 words -> both phases bank-conflict-free.
// ---------------------------------------------------------------------------
__global__ void __launch_bounds__(128, 3) sat_tile(const float4* __restrict__ feat) {
    extern __shared__ float sm[];                 // 32 * RS words = 67584 B
    int b    = blockIdx.x;
    int dgrp = b & 15;                            // 16 channel groups of 16
    int tj   = (b >> 4) & 7;
    int ti   = b >> 7;
    int t    = threadIdx.x;
    int kw4  = t & 3;                             // float4 word within group
    int u    = t >> 2;                            // 0..31: row (A) / col (B)
    int h0 = ti * 32, w0 = tj * 32;
    int c0 = dgrp * 4;                            // channel offset in float4 units

    // Phase A: row scan, prefetch depth 8.
    {
        const float4* __restrict__ src =
            feat + ((size_t)(h0 + u) * WW + w0) * D4 + c0 + kw4;
        float* __restrict__ srow = &sm[u * RS + kw4 * 4];
        float4 acc = make_float4(0.f, 0.f, 0.f, 0.f);
        float4 buf[8];
#pragma unroll 1
        for (int cc = 0; cc < 32; cc += 8) {
#pragma unroll
            for (int j = 0; j < 8; ++j)
                buf[j] = __ldcs(&src[(size_t)(cc + j) * D4]);
#pragma unroll
            for (int j = 0; j < 8; ++j) {
                acc4(acc, buf[j]);
                *reinterpret_cast<float4*>(&srow[(cc + j) * 16]) = acc;
            }
        }
    }
    __syncthreads();

    // Phase B: col scan, prefetch depth 8 on smem.
    {
        float4* __restrict__ dst =
            g_part + ((size_t)h0 * WW + w0 + u) * D4 + c0 + kw4;
        const float* __restrict__ scol = &sm[u * 16 + kw4 * 4];
        float4 acc = make_float4(0.f, 0.f, 0.f, 0.f);
        float4 buf[8];
#pragma unroll 1
        for (int rr = 0; rr < 32; rr += 8) {
#pragma unroll
            for (int j = 0; j < 8; ++j)
                buf[j] = *reinterpret_cast<const float4*>(&scol[(rr + j) * RS]);
#pragma unroll
            for (int j = 0; j < 8; ++j) {
                acc4(acc, buf[j]);
                dst[(size_t)(rr + j) * WW * D4] = acc;
            }
        }
    }
}

// ---------------------------------------------------------------------------
// Fixups: rowcum / colcum / blockcum from tile edges in g_part (L2-resident).
// Unconditional loads (MLP=7) + predicated adds.
// ---------------------------------------------------------------------------
__global__ void __launch_bounds__(256) fixups() {
    int flat = blockIdx.x * 256 + threadIdx.x;
    if (flat < 131072) {                       // rowcum: left strip sums at row r
        int d4 = flat & 63, r = (flat >> 6) & 31, tj = (flat >> 11) & 7, ti = flat >> 14;
        float4 acc = make_float4(0.f, 0.f, 0.f, 0.f);
#pragma unroll
        for (int s = 0; s < 7; ++s) {
            float4 v = g_part[((size_t)(ti * 32 + r) * WW + s * 32 + 31) * D4 + d4];
            if (s < tj) acc4(acc, v);
        }
        g_rowcum[((ti * 8 + tj) * 32 + r) * 64 + d4] = acc;
    } else if (flat < 262144) {                // colcum: above strip sums at col c
        int f = flat - 131072;
        int d4 = f & 63, c = (f >> 6) & 31, tj = (f >> 11) & 7, ti = f >> 14;
        float4 acc = make_float4(0.f, 0.f, 0.f, 0.f);
#pragma unroll
        for (int s = 0; s < 7; ++s) {
            float4 v = g_part[((size_t)(s * 32 + 31) * WW + tj * 32 + c) * D4 + d4];
            if (s < ti) acc4(acc, v);
        }
        g_colcum[((ti * 8 + tj) * 32 + c) * 64 + d4] = acc;
    } else {                                   // blockcum: 2D prefix of tile totals
        int f = flat - 262144;
        int d4 = f & 63, tj = (f >> 6) & 7, ti = f >> 9;
        float4 acc = make_float4(0.f, 0.f, 0.f, 0.f);
#pragma unroll
        for (int si = 0; si < 7; ++si)
#pragma unroll
            for (int sj = 0; sj < 7; ++sj) {
                float4 v = g_part[((size_t)(si * 32 + 31) * WW + sj * 32 + 31) * D4 + d4];
                if (si < ti && sj < tj) acc4(acc, v);
            }
        g_blockcum[(ti * 8 + tj) * 64 + d4] = acc;
    }
}

// Full SAT(r, c) = tile partial + left strip + above strip + above-left blocks.
__device__ __forceinline__ float4 satval(int r, int c, int d4) {
    int ti = r >> 5, tj = c >> 5;
    float4 v = g_part[((size_t)r * WW + c) * D4 + d4];
    acc4(v, g_rowcum[((ti * 8 + tj) * 32 + (r & 31)) * 64 + d4]);
    acc4(v, g_colcum[((ti * 8 + tj) * 32 + (c & 31)) * 64 + d4]);
    acc4(v, g_blockcum[(ti * 8 + tj) * 64 + d4]);
    return v;
}

// ---------------------------------------------------------------------------
// Gather: 4 boxes per block, 64 float4 lanes per box, <=16 corner loads (L2).
// ---------------------------------------------------------------------------
__global__ void __launch_bounds__(256) roi_gather(const float* __restrict__ boxes,
                                                  float4* __restrict__ out) {
    int n  = blockIdx.x * 4 + (threadIdx.x >> 6);
    int d4 = threadIdx.x & 63;

    float x1 = boxes[n * 4 + 0];
    float y1 = boxes[n * 4 + 1];
    float x2 = boxes[n * 4 + 2];
    float y2 = boxes[n * 4 + 3];

    // _bounds: lo = max(0, floor(lo_f*256)); hi = rint(hi_f*256 + 0.5)
    //          hi = min(256, max(lo+1, hi)). No FMA contraction (match jax).
    int clo = max(0, (int)floorf(__fmul_rn(x1, 256.0f)));
    int chi = (int)rintf(__fadd_rn(__fmul_rn(x2, 256.0f), 0.5f));
    chi = min(WW, max(clo + 1, chi));

    int rlo = max(0, (int)floorf(__fmul_rn(y1, 256.0f)));
    int rhi = (int)rintf(__fadd_rn(__fmul_rn(y2, 256.0f), 0.5f));
    rhi = min(HH, max(rlo + 1, rhi));

    float4 s = satval(rhi - 1, chi - 1, d4);
    if (rlo > 0) {
        float4 a = satval(rlo - 1, chi - 1, d4);
        s.x -= a.x; s.y -= a.y; s.z -= a.z; s.w -= a.w;
    }
    if (clo > 0) {
        float4 bb = satval(rhi - 1, clo - 1, d4);
        s.x -= bb.x; s.y -= bb.y; s.z -= bb.z; s.w -= bb.w;
        if (rlo > 0) acc4(s, satval(rlo - 1, clo - 1, d4));
    }

    float inv = 1.0f / (float)((rhi - rlo) * (chi - clo));
    s.x *= inv; s.y *= inv; s.z *= inv; s.w *= inv;
    out[(size_t)n * D4 + d4] = s;
}

extern "C" void kernel_launch(void* const* d_in, const int* in_sizes, int n_in,
                              void* d_out, int out_size) {
    const float4* feat  = (const float4*)d_in[0];   // (256,256,256) fp32
    const float*  boxes = (const float*)d_in[1];    // (2048,4) fp32
    float4* out = (float4*)d_out;                   // (2048,256) fp32

    const int smem = 32 * RS * 4;                   // 67584 B -> 3 blocks/SM
    cudaFuncSetAttribute(sat_tile, cudaFuncAttributeMaxDynamicSharedMemorySize, smem);

    sat_tile<<<1024, 128, smem>>>(feat);
    fixups<<<1040, 256>>>();                        // 262144 + 4096 threads
    roi_gather<<<NB / 4, 256>>>(boxes, out);
}

// round 8
// speedup vs baseline: 1.6110x; 1.3839x over previous
#include <cuda_runtime.h>
#include <cstdint>

#define HH 256
#define WW 256
#define D4 64            // 256 channels as float4
#define NB 2048
#define RS 528           // smem row stride in words: 528 % 32 == 16

// 64 MB tile-partial SAT + cum tables (2MB + 2MB + 64KB).
__device__ float4 g_part[(size_t)HH * WW * D4];
__device__ float4 g_rowcum[8 * 8 * 32 * D4];   // [ti][tj][r][d4]
__device__ float4 g_colcum[8 * 8 * 32 * D4];   // [ti][tj][c][d4]
__device__ float4 g_blockcum[8 * 8 * D4];      // [ti][tj][d4]

__device__ __forceinline__ void acc4(float4& a, const float4 v) {
    a.x += v.x; a.y += v.y; a.z += v.z; a.w += v.w;
}

__device__ __forceinline__ uint32_t smem_u32(const void* p) {
    return (uint32_t)__cvta_generic_to_shared(p);
}

// ---------------------------------------------------------------------------
// Tile SAT: 32x32 pixels x 16 channels per block, 1024 blocks x 128 threads.
// Stage: cp.async.cg 16B gmem->smem — completion via commit group, NOT
// registers, so the whole 64KB tile is in flight at once (no MLP ceiling).
// Phase A: row prefix smem->smem (LDS.128/STS.128 in place, conflict-free).
// Phase B: col prefix smem->gmem (LDS.128 batched + STG.128).
// ---------------------------------------------------------------------------
__global__ void __launch_bounds__(128, 3) sat_tile(const float4* __restrict__ feat) {
    extern __shared__ float sm[];                 // 32 * RS words = 67584 B
    int b    = blockIdx.x;
    int dgrp = b & 15;                            // 16 channel groups of 16
    int tj   = (b >> 4) & 7;
    int ti   = b >> 7;
    int t    = threadIdx.x;
    int kw4  = t & 3;                             // float4 word within group
    int u    = t >> 2;                            // 0..31: row (A) / col (B)
    int h0 = ti * 32, w0 = tj * 32;
    int c0 = dgrp * 4;                            // channel offset in float4 units

    // Stage: async-copy this thread's 32 float4s (one per column) into smem.
    {
        const float4* __restrict__ src =
            feat + ((size_t)(h0 + u) * WW + w0) * D4 + c0 + kw4;
        uint32_t dst = smem_u32(&sm[u * RS + kw4 * 4]);
#pragma unroll
        for (int c = 0; c < 32; ++c) {
            asm volatile("cp.async.cg.shared.global [%0], [%1], 16;\n"
                         :: "r"(dst + c * 64), "l"(src + (size_t)c * D4)
                         : "memory");
        }
        asm volatile("cp.async.commit_group;\n" ::: "memory");
        asm volatile("cp.async.wait_group 0;\n" ::: "memory");
    }
    __syncthreads();

    // Phase A: row scan in place (read raw, write prefix), batch 8.
    {
        float* __restrict__ srow = &sm[u * RS + kw4 * 4];
        float4 acc = make_float4(0.f, 0.f, 0.f, 0.f);
        float4 buf[8];
#pragma unroll 1
        for (int cc = 0; cc < 32; cc += 8) {
#pragma unroll
            for (int j = 0; j < 8; ++j)
                buf[j] = *reinterpret_cast<const float4*>(&srow[(cc + j) * 16]);
#pragma unroll
            for (int j = 0; j < 8; ++j) {
                acc4(acc, buf[j]);
                *reinterpret_cast<float4*>(&srow[(cc + j) * 16]) = acc;
            }
        }
    }
    __syncthreads();

    // Phase B: col scan, batch 8 on smem, stream out to g_part.
    {
        float4* __restrict__ dst =
            g_part + ((size_t)h0 * WW + w0 + u) * D4 + c0 + kw4;
        const float* __restrict__ scol = &sm[u * 16 + kw4 * 4];
        float4 acc = make_float4(0.f, 0.f, 0.f, 0.f);
        float4 buf[8];
#pragma unroll 1
        for (int rr = 0; rr < 32; rr += 8) {
#pragma unroll
            for (int j = 0; j < 8; ++j)
                buf[j] = *reinterpret_cast<const float4*>(&scol[(rr + j) * RS]);
#pragma unroll
            for (int j = 0; j < 8; ++j) {
                acc4(acc, buf[j]);
                dst[(size_t)(rr + j) * WW * D4] = acc;
            }
        }
    }
}

// ---------------------------------------------------------------------------
// Fixups: rowcum / colcum / blockcum from tile edges in g_part (L2-resident).
// Unconditional loads (MLP=7) + predicated adds.
// ---------------------------------------------------------------------------
__global__ void __launch_bounds__(256) fixups() {
    int flat = blockIdx.x * 256 + threadIdx.x;
    if (flat < 131072) {                       // rowcum: left strip sums at row r
        int d4 = flat & 63, r = (flat >> 6) & 31, tj = (flat >> 11) & 7, ti = flat >> 14;
        float4 acc = make_float4(0.f, 0.f, 0.f, 0.f);
#pragma unroll
        for (int s = 0; s < 7; ++s) {
            float4 v = g_part[((size_t)(ti * 32 + r) * WW + s * 32 + 31) * D4 + d4];
            if (s < tj) acc4(acc, v);
        }
        g_rowcum[((ti * 8 + tj) * 32 + r) * 64 + d4] = acc;
    } else if (flat < 262144) {                // colcum: above strip sums at col c
        int f = flat - 131072;
        int d4 = f & 63, c = (f >> 6) & 31, tj = (f >> 11) & 7, ti = f >> 14;
        float4 acc = make_float4(0.f, 0.f, 0.f, 0.f);
#pragma unroll
        for (int s = 0; s < 7; ++s) {
            float4 v = g_part[((size_t)(s * 32 + 31) * WW + tj * 32 + c) * D4 + d4];
            if (s < ti) acc4(acc, v);
        }
        g_colcum[((ti * 8 + tj) * 32 + c) * 64 + d4] = acc;
    } else {                                   // blockcum: 2D prefix of tile totals
        int f = flat - 262144;
        int d4 = f & 63, tj = (f >> 6) & 7, ti = f >> 9;
        float4 acc = make_float4(0.f, 0.f, 0.f, 0.f);
#pragma unroll
        for (int si = 0; si < 7; ++si)
#pragma unroll
            for (int sj = 0; sj < 7; ++sj) {
                float4 v = g_part[((size_t)(si * 32 + 31) * WW + sj * 32 + 31) * D4 + d4];
                if (si < ti && sj < tj) acc4(acc, v);
            }
        g_blockcum[(ti * 8 + tj) * 64 + d4] = acc;
    }
}

// Full SAT(r, c) = tile partial + left strip + above strip + above-left blocks.
__device__ __forceinline__ float4 satval(int r, int c, int d4) {
    int ti = r >> 5, tj = c >> 5;
    float4 v = g_part[((size_t)r * WW + c) * D4 + d4];
    acc4(v, g_rowcum[((ti * 8 + tj) * 32 + (r & 31)) * 64 + d4]);
    acc4(v, g_colcum[((ti * 8 + tj) * 32 + (c & 31)) * 64 + d4]);
    acc4(v, g_blockcum[(ti * 8 + tj) * 64 + d4]);
    return v;
}

// ---------------------------------------------------------------------------
// Gather: 4 boxes per block, 64 float4 lanes per box, <=16 corner loads (L2).
// ---------------------------------------------------------------------------
__global__ void __launch_bounds__(256) roi_gather(const float* __restrict__ boxes,
                                                  float4* __restrict__ out) {
    int n  = blockIdx.x * 4 + (threadIdx.x >> 6);
    int d4 = threadIdx.x & 63;

    float x1 = boxes[n * 4 + 0];
    float y1 = boxes[n * 4 + 1];
    float x2 = boxes[n * 4 + 2];
    float y2 = boxes[n * 4 + 3];

    // _bounds: lo = max(0, floor(lo_f*256)); hi = rint(hi_f*256 + 0.5)
    //          hi = min(256, max(lo+1, hi)). No FMA contraction (match jax).
    int clo = max(0, (int)floorf(__fmul_rn(x1, 256.0f)));
    int chi = (int)rintf(__fadd_rn(__fmul_rn(x2, 256.0f), 0.5f));
    chi = min(WW, max(clo + 1, chi));

    int rlo = max(0, (int)floorf(__fmul_rn(y1, 256.0f)));
    int rhi = (int)rintf(__fadd_rn(__fmul_rn(y2, 256.0f), 0.5f));
    rhi = min(HH, max(rlo + 1, rhi));

    float4 s = satval(rhi - 1, chi - 1, d4);
    if (rlo > 0) {
        float4 a = satval(rlo - 1, chi - 1, d4);
        s.x -= a.x; s.y -= a.y; s.z -= a.z; s.w -= a.w;
    }
    if (clo > 0) {
        float4 bb = satval(rhi - 1, clo - 1, d4);
        s.x -= bb.x; s.y -= bb.y; s.z -= bb.z; s.w -= bb.w;
        if (rlo > 0) acc4(s, satval(rlo - 1, clo - 1, d4));
    }

    float inv = 1.0f / (float)((rhi - rlo) * (chi - clo));
    s.x *= inv; s.y *= inv; s.z *= inv; s.w *= inv;
    out[(size_t)n * D4 + d4] = s;
}

extern "C" void kernel_launch(void* const* d_in, const int* in_sizes, int n_in,
                              void* d_out, int out_size) {
    const float4* feat  = (const float4*)d_in[0];   // (256,256,256) fp32
    const float*  boxes = (const float*)d_in[1];    // (2048,4) fp32
    float4* out = (float4*)d_out;                   // (2048,256) fp32

    const int smem = 32 * RS * 4;                   // 67584 B -> 3 blocks/SM
    cudaFuncSetAttribute(sat_tile, cudaFuncAttributeMaxDynamicSharedMemorySize, smem);

    sat_tile<<<1024, 128, smem>>>(feat);
    fixups<<<1040, 256>>>();                        // 262144 + 4096 threads
    roi_gather<<<NB / 4, 256>>>(boxes, out);
}